// round 9
// baseline (speedup 1.0000x reference)
#include <cuda_runtime.h>

// DeepSets: out[s,f] = sx_s*W[0,f] + sy_s*W[1,f] + cnt_s*b[f]
// Linearity: segment_sum(xW+b) == segment_sum(x)@W + cnt*b.
//
// ONE persistent kernel, one resident wave (608 CTAs x 256 thr, 4 CTAs/SM):
//  Phase 1: each warp streams its contiguous float4 range while CACHING
//           per-position pair-sums in registers (ax/ay[16]). Per-segment
//           suffixes are then pure-ALU register sweeps — NO second memory
//           pass. Boundary located by a warp-wide lower_bound in the warp's
//           own tiny ids range; odd-boundary fixed by one L2-hot scalar load.
//  Grid barrier (generation counter, wrap-safe, never reset).
//  Phase 2: epilogue expands to [4096,64] with float4 stores; accumulators
//           reset by the same threads that read them (zero-at-entry across
//           graph replays; device globals start zeroed).

#define FEAT_OUT 64
#define NSEG_MAX 4096
#define K2_CTAS 608
#define K2_THREADS 256
#define K2_WARPS (K2_CTAS * (K2_THREADS / 32))
#define KMAX 16
#define CHUNK (32 * KMAX)   // 512 float4 per register-cached chunk

__device__ float    g_px[NSEG_MAX];
__device__ float    g_py[NSEG_MAX];
__device__ int      g_cnt[NSEG_MAX];
__device__ unsigned g_arrive;   // monotonic generation barrier counter

__device__ __forceinline__ float warp_sum(float v)
{
    #pragma unroll
    for (int o = 16; o > 0; o >>= 1) v += __shfl_xor_sync(0xFFFFFFFFu, v, o);
    return v;
}

// Warp-collective lower_bound of `target` in ids[lo,hi); all lanes return the
// same value. 2 rounds for ranges < 1089.
__device__ __forceinline__ int warp_lower_bound(const int* __restrict__ ids,
                                                int lo, int hi, int target)
{
    const int lane = threadIdx.x & 31;
    while (hi > lo) {
        const int m = hi - lo;
        const int p = lo + (int)(((long long)m * (lane + 1)) / 33);
        const int v = __ldg(&ids[p]);
        const unsigned pred = __ballot_sync(0xFFFFFFFFu, v < target);
        const int c = __popc(pred);
        int nlo, nhi;
        if (c == 0)  nlo = lo; else nlo = lo + (int)(((long long)m * c) / 33) + 1;
        if (c == 32) nhi = hi; else nhi = lo + (int)(((long long)m * (c + 1)) / 33);
        lo = nlo; hi = nhi;
    }
    return lo;
}

__global__ __launch_bounds__(K2_THREADS, 4)
void deepsets_fused_kernel(const float4* __restrict__ xb,   // [N/2] point pairs
                           const float2* __restrict__ x2,   // [N]
                           const int*    __restrict__ ids,  // [N] sorted
                           const float*  __restrict__ W,    // [2,64]
                           const float*  __restrict__ b,    // [64]
                           float*        __restrict__ out,  // [nseg,64]
                           int N, int NF4, int num_segments)
{
    const int lane = threadIdx.x & 31;
    const int gw   = blockIdx.x * (K2_THREADS / 32) + (threadIdx.x >> 5);

    if ((N & 1) && gw == 0 && lane == 0) {
        const int s = __ldg(&ids[N - 1]);
        const float2 p = __ldg(&x2[N - 1]);
        atomicAdd(&g_px[s], p.x);
        atomicAdd(&g_py[s], p.y);
        atomicAdd(&g_cnt[s], 1);
    }

    const int Q  = (NF4 + K2_WARPS - 1) / K2_WARPS;
    const int f0 = gw * Q;
    const int f1 = min(f0 + Q, NF4);

    // Register-cached chunks (exactly one for N=4M: Q=412 <= 512).
    for (int c0 = f0; c0 < f1; c0 += CHUNK) {
        const int c1 = min(c0 + CHUNK, f1);
        const int q0 = 2 * c0;
        const int q1 = 2 * c1;
        // Endpoint id loads issue now; consumed after the stream.
        const int s_lo = __ldg(&ids[q0]);
        const int s_hi = __ldg(&ids[q1 - 1]);

        // ---- Stream + register cache (MLP-4 groups) ----------------------
        float ax[KMAX], ay[KMAX];
        float tx = 0.f, ty = 0.f;
        #pragma unroll
        for (int k = 0; k < KMAX; k += 4) {
            const int j0 = c0 + lane + 32 * k;
            const int j1 = j0 + 32, j2 = j0 + 64, j3 = j0 + 96;
            float4 v0 = make_float4(0.f,0.f,0.f,0.f);
            float4 v1 = make_float4(0.f,0.f,0.f,0.f);
            float4 v2 = make_float4(0.f,0.f,0.f,0.f);
            float4 v3 = make_float4(0.f,0.f,0.f,0.f);
            if (j0 < c1) v0 = __ldg(&xb[j0]);
            if (j1 < c1) v1 = __ldg(&xb[j1]);
            if (j2 < c1) v2 = __ldg(&xb[j2]);
            if (j3 < c1) v3 = __ldg(&xb[j3]);
            ax[k]   = v0.x + v0.z;  ay[k]   = v0.y + v0.w;
            ax[k+1] = v1.x + v1.z;  ay[k+1] = v1.y + v1.w;
            ax[k+2] = v2.x + v2.z;  ay[k+2] = v2.y + v2.w;
            ax[k+3] = v3.x + v3.z;  ay[k+3] = v3.y + v3.w;
            tx += ax[k] + ax[k+1] + ax[k+2] + ax[k+3];
            ty += ay[k] + ay[k+1] + ay[k+2] + ay[k+3];
        }
        tx = warp_sum(tx); ty = warp_sum(ty);

        // ---- Boundary suffixes: pure register sweeps ----------------------
        const int nseg = s_hi - s_lo + 1;
        float prevSx = tx, prevSy = ty;   // suffix from q0 == chunk total
        int   prevB  = q0;
        int   searchLo = q0 + 1;

        for (int m = 1; m < nseg; m++) {
            const int Bm = warp_lower_bound(ids, searchLo, q1, s_lo + m);
            searchLo = Bm;
            const int jB = Bm >> 1;       // f4 index containing point Bm
            float sx = 0.f, sy = 0.f;
            #pragma unroll
            for (int k = 0; k < KMAX; k++) {
                const int j = c0 + lane + 32 * k;
                if (j >= jB) { sx += ax[k]; sy += ay[k]; }
            }
            sx = warp_sum(sx); sy = warp_sum(sy);
            if (lane == 0) {
                if (Bm & 1) {
                    // f4 jB's even point (index Bm-1) belongs to the PREVIOUS
                    // segment; remove it from the suffix. L2-hot scalar load.
                    const float2 pc = __ldg(&x2[Bm - 1]);
                    sx -= pc.x; sy -= pc.y;
                }
                atomicAdd(&g_px[s_lo + m - 1],  prevSx - sx);
                atomicAdd(&g_py[s_lo + m - 1],  prevSy - sy);
                atomicAdd(&g_cnt[s_lo + m - 1], Bm - prevB);
                prevSx = sx; prevSy = sy; prevB = Bm;
            }
            // keep lanes' prev in sync for next iteration
            prevSx = __shfl_sync(0xFFFFFFFFu, prevSx, 0);
            prevSy = __shfl_sync(0xFFFFFFFFu, prevSy, 0);
            prevB  = __shfl_sync(0xFFFFFFFFu, prevB, 0);
        }
        if (lane == 0) {
            atomicAdd(&g_px[s_hi],  prevSx);
            atomicAdd(&g_py[s_hi],  prevSy);
            atomicAdd(&g_cnt[s_hi], q1 - prevB);
        }
    }

    // ---------------- Grid barrier (generation counter) ------------------
    __syncthreads();
    if (threadIdx.x == 0) {
        __threadfence();
        const unsigned ticket = atomicAdd(&g_arrive, 1u);
        const unsigned target = (ticket / K2_CTAS + 1u) * K2_CTAS;
        while ((int)(*(volatile unsigned*)&g_arrive - target) < 0)
            __nanosleep(64);
        __threadfence();
    }
    __syncthreads();

    // ---------------- Phase 2: epilogue (float4 per thread) --------------
    const int n_out4 = num_segments * (FEAT_OUT / 4);   // 65536
    for (int gid = blockIdx.x * K2_THREADS + threadIdx.x; gid < n_out4;
         gid += K2_CTAS * K2_THREADS) {
        const int s  = gid >> 4;           // 16 threads (one float4 each) / seg
        const int fq = (gid & 15) << 2;    // feature quad base
        const float sx  = g_px[s];
        const float sy  = g_py[s];
        const float cnt = (float)g_cnt[s];
        const float4 w0 = __ldg((const float4*)&W[fq]);
        const float4 w1 = __ldg((const float4*)&W[FEAT_OUT + fq]);
        const float4 bb = __ldg((const float4*)&b[fq]);
        float4 o;
        o.x = fmaf(sx, w0.x, fmaf(sy, w1.x, cnt * bb.x));
        o.y = fmaf(sx, w0.y, fmaf(sy, w1.y, cnt * bb.y));
        o.z = fmaf(sx, w0.z, fmaf(sy, w1.z, cnt * bb.z));
        o.w = fmaf(sx, w0.w, fmaf(sy, w1.w, cnt * bb.w));
        reinterpret_cast<float4*>(out)[gid] = o;
    }
    __syncthreads();   // this block's reads of its segments are complete

    // Reset by the SAME threads that read each segment (16 threads/segment,
    // contiguous within a block since K2_THREADS % 16 == 0). Race-free.
    for (int gid = blockIdx.x * K2_THREADS + threadIdx.x; gid < n_out4;
         gid += K2_CTAS * K2_THREADS) {
        const int s = gid >> 4;
        const int r = gid & 15;
        if      (r == 0) g_px[s]  = 0.f;
        else if (r == 1) g_py[s]  = 0.f;
        else if (r == 2) g_cnt[s] = 0;
    }
}

extern "C" void kernel_launch(void* const* d_in, const int* in_sizes, int n_in,
                              void* d_out, int out_size)
{
    const float* xf  = (const float*)d_in[0];    // [N,2]
    const int*   ids = (const int*)d_in[1];      // [N] sorted
    const float* W   = (const float*)d_in[2];    // [2,64]
    const float* b   = (const float*)d_in[3];    // [64]
    float* out = (float*)d_out;

    const int N   = in_sizes[0] / 2;
    const int NF4 = N / 2;
    const int num_segments = out_size / FEAT_OUT;   // 4096

    deepsets_fused_kernel<<<K2_CTAS, K2_THREADS>>>(
        (const float4*)xf, (const float2*)xf, ids, W, b, out,
        N, NF4, num_segments);
}